// round 1
// baseline (speedup 1.0000x reference)
#include <cuda_runtime.h>
#include <cstdint>

#define ROWS 16384      // B*S = 4*4096
#define CH   4096       // csum channels
#define NHD  8
#define IGD  128
#define TGD  384        // 3*IG
#define FGD  512
#define ISZ  1024

// ---------------- scratch (static device globals; no allocs) ----------------
__device__ float g_csum[(size_t)ROWS * CH];        // 256 MB  (also holds cumsum in-place)
__device__ float g_cell[(size_t)ROWS * NHD * TGD]; // 192 MB  cell_i = [lcg | out_x | rcg] per head
__device__ float g_lci [(size_t)ROWS * ISZ];       // 64 MB
__device__ float g_rci [(size_t)ROWS * ISZ];       // 64 MB
__device__ float g_gbuf[(size_t)ROWS * NHD * TGD]; // 192 MB  gates
__device__ float g_hbuf[(size_t)ROWS * NHD * FGD]; // 256 MB  ffn hidden
__device__ float g_xbuf[(size_t)ROWS * ISZ];       // 64 MB
__device__ float g_pre [(size_t)ROWS * ISZ];       // 64 MB   combine output

// ---------------- block reduce (sum, sumsq) ----------------
__device__ __forceinline__ void block_reduce2(float& a, float& b) {
    __shared__ float sh[64];
    int lane = threadIdx.x & 31, wid = threadIdx.x >> 5;
#pragma unroll
    for (int o = 16; o > 0; o >>= 1) {
        a += __shfl_xor_sync(0xffffffffu, a, o);
        b += __shfl_xor_sync(0xffffffffu, b, o);
    }
    if (lane == 0) { sh[wid] = a; sh[32 + wid] = b; }
    __syncthreads();
    if (threadIdx.x < 32) {
        a = (lane < 8) ? sh[lane] : 0.f;
        b = (lane < 8) ? sh[32 + lane] : 0.f;
#pragma unroll
        for (int o = 4; o > 0; o >>= 1) {
            a += __shfl_xor_sync(0xffffffffu, a, o);
            b += __shfl_xor_sync(0xffffffffu, b, o);
        }
        if (lane == 0) { sh[0] = a; sh[32] = b; }
    }
    __syncthreads();
    a = sh[0]; b = sh[32];
}

// ---------------- SGEMM 128x128x8, 256 threads, 8x8 per thread ----------------
// FLAGS: 1 = row-mask zero (after bias), 2 = add residual, 4 = remap cols into cell_i slot
template <int FLAGS>
__global__ void __launch_bounds__(256, 2) sgemm_k(
    const float* __restrict__ A, int lda, long aoff,
    const float* __restrict__ B, long boff,
    const float* __restrict__ bias, int biasoff,
    float* __restrict__ C, int ldc, long coff,
    int N, int K,
    const unsigned char* __restrict__ mask,
    const float* __restrict__ resid)
{
    A    += (long)blockIdx.z * aoff;
    B    += (long)blockIdx.z * boff;
    bias += (long)blockIdx.z * biasoff;
    C    += (long)blockIdx.z * coff;

    __shared__ float As[8][128];
    __shared__ float Bs[8][128];

    const int tid = threadIdx.x;
    const int m0 = blockIdx.y * 128;
    const int n0 = blockIdx.x * 128;

    const int arow = tid >> 1, acol = (tid & 1) * 4;
    const int brow = tid >> 5, bcol = (tid & 31) * 4;

    const float* Aptr = A + (long)(m0 + arow) * lda + acol;
    const float* Bptr = B + (long)brow * N + n0 + bcol;

    float acc[8][8];
#pragma unroll
    for (int i = 0; i < 8; i++)
#pragma unroll
        for (int j = 0; j < 8; j++) acc[i][j] = 0.f;

    const int ty = tid >> 4, tx = tid & 15;

    for (int k0 = 0; k0 < K; k0 += 8) {
        float4 av = *(const float4*)Aptr;
        float4 bv = *(const float4*)Bptr;
        As[acol + 0][arow] = av.x;
        As[acol + 1][arow] = av.y;
        As[acol + 2][arow] = av.z;
        As[acol + 3][arow] = av.w;
        *(float4*)&Bs[brow][bcol] = bv;
        __syncthreads();
#pragma unroll
        for (int k = 0; k < 8; k++) {
            float ra[8], rb[8];
            *(float4*)(ra)     = *(const float4*)&As[k][ty * 8];
            *(float4*)(ra + 4) = *(const float4*)&As[k][ty * 8 + 4];
            *(float4*)(rb)     = *(const float4*)&Bs[k][tx * 8];
            *(float4*)(rb + 4) = *(const float4*)&Bs[k][tx * 8 + 4];
#pragma unroll
            for (int i = 0; i < 8; i++)
#pragma unroll
                for (int j = 0; j < 8; j++) acc[i][j] += ra[i] * rb[j];
        }
        __syncthreads();
        Aptr += 8;
        Bptr += (long)8 * N;
    }

#pragma unroll
    for (int i = 0; i < 8; i++) {
        long row = m0 + ty * 8 + i;
        float zf = 1.f;
        if (FLAGS & 1) zf = mask[row] ? 0.f : 1.f;
#pragma unroll
        for (int jj = 0; jj < 8; jj += 4) {
            int n = n0 + tx * 8 + jj;
            float4 bv = *(const float4*)(bias + n);
            float4 o;
            o.x = acc[i][jj + 0] + bv.x;
            o.y = acc[i][jj + 1] + bv.y;
            o.z = acc[i][jj + 2] + bv.z;
            o.w = acc[i][jj + 3] + bv.w;
            if (FLAGS & 1) { o.x *= zf; o.y *= zf; o.z *= zf; o.w *= zf; }
            if (FLAGS & 2) {
                float4 rv = *(const float4*)(resid + row * N + n);
                o.x += rv.x; o.y += rv.y; o.z += rv.z; o.w += rv.w;
            }
            int cn = n;
            if (FLAGS & 4) cn = (n >> 7) * TGD + IGD + (n & 127);
            *(float4*)(C + row * ldc + cn) = o;
        }
    }
}

// ---------------- cumsum along S (fwd for ch<2048, reverse for ch>=2048) ----------------
__global__ void __launch_bounds__(256) cumsum_k(float* __restrict__ buf) {
    int idx = blockIdx.x * 256 + threadIdx.x;   // 0 .. 4*4096-1
    int b = idx >> 12, c = idx & 4095;
    float* p = buf + ((size_t)b << 24) + c;     // b*4096*4096 + c
    float acc = 0.f;
    if (c < 2048) {
#pragma unroll 8
        for (int s = 0; s < 4096; s++) { acc += p[(size_t)s * CH]; p[(size_t)s * CH] = acc; }
    } else {
#pragma unroll 8
        for (int s = 4095; s >= 0; s--) { acc += p[(size_t)s * CH]; p[(size_t)s * CH] = acc; }
    }
}

// ---------------- LN over lc/rc (2048 each), scatter into cell_i + relu'd i-parts ----------------
__global__ void __launch_bounds__(256) ln_lcrc_k(
    const float* __restrict__ gl, const float* __restrict__ bl,
    const float* __restrict__ gr, const float* __restrict__ br_)
{
    const int row = blockIdx.x, side = blockIdx.y;   // side 0 = lc, 1 = rc
    const float4* x4 = (const float4*)(g_csum + (size_t)row * CH + side * 2048);
    float4 v[2];
    float s = 0.f, ss = 0.f;
#pragma unroll
    for (int k = 0; k < 2; k++) {
        v[k] = x4[threadIdx.x + k * 256];
        s  += v[k].x + v[k].y + v[k].z + v[k].w;
        ss += v[k].x * v[k].x + v[k].y * v[k].y + v[k].z * v[k].z + v[k].w * v[k].w;
    }
    block_reduce2(s, ss);
    float m  = s * (1.f / 2048.f);
    float rs = rsqrtf(ss * (1.f / 2048.f) - m * m + 1e-6f);

    const float4* g4 = (const float4*)(side ? gr  : gl);
    const float4* b4 = (const float4*)(side ? br_ : bl);
    float* ibuf = side ? g_rci : g_lci;
#pragma unroll
    for (int k = 0; k < 2; k++) {
        int c4 = threadIdx.x + k * 256;
        int c  = c4 * 4;
        float4 gv = g4[c4], bv = b4[c4], xv = v[k];
        float4 o;
        o.x = (xv.x - m) * rs * gv.x + bv.x;
        o.y = (xv.y - m) * rs * gv.y + bv.y;
        o.z = (xv.z - m) * rs * gv.z + bv.z;
        o.w = (xv.w - m) * rs * gv.w + bv.w;
        if (c < 1024) {   // gate part -> cell_i  [h*384 + side*256 + ig]
            int h = c >> 7, ig = c & 127;
            *(float4*)(g_cell + (size_t)row * (NHD * TGD) + h * TGD + side * 256 + ig) = o;
        } else {          // input part -> relu -> lci/rci
            o.x = fmaxf(o.x, 0.f); o.y = fmaxf(o.y, 0.f);
            o.z = fmaxf(o.z, 0.f); o.w = fmaxf(o.w, 0.f);
            *(float4*)(ibuf + (size_t)row * ISZ + (c - 1024)) = o;
        }
    }
}

// ---------------- LN over full 3072 gates + sigmoid, in place ----------------
__global__ void __launch_bounds__(256) ln_g_k(const float* __restrict__ gg,
                                              const float* __restrict__ bg) {
    const int row = blockIdx.x;
    float4* x4 = (float4*)(g_gbuf + (size_t)row * (NHD * TGD));
    float4 v[3];
    float s = 0.f, ss = 0.f;
#pragma unroll
    for (int k = 0; k < 3; k++) {
        v[k] = x4[threadIdx.x + k * 256];
        s  += v[k].x + v[k].y + v[k].z + v[k].w;
        ss += v[k].x * v[k].x + v[k].y * v[k].y + v[k].z * v[k].z + v[k].w * v[k].w;
    }
    block_reduce2(s, ss);
    float m  = s * (1.f / 3072.f);
    float rs = rsqrtf(ss * (1.f / 3072.f) - m * m + 1e-6f);
    const float4* g4 = (const float4*)gg;
    const float4* b4 = (const float4*)bg;
#pragma unroll
    for (int k = 0; k < 3; k++) {
        int c4 = threadIdx.x + k * 256;
        float4 gv = g4[c4], bv = b4[c4], xv = v[k];
        float4 o;
        o.x = 1.f / (1.f + expf(-((xv.x - m) * rs * gv.x + bv.x)));
        o.y = 1.f / (1.f + expf(-((xv.y - m) * rs * gv.y + bv.y)));
        o.z = 1.f / (1.f + expf(-((xv.z - m) * rs * gv.z + bv.z)));
        o.w = 1.f / (1.f + expf(-((xv.w - m) * rs * gv.w + bv.w)));
        x4[c4] = o;
    }
}

// ---------------- LN over full 4096 ffn hidden + relu, in place ----------------
__global__ void __launch_bounds__(256) ln_f_k(const float* __restrict__ gf,
                                              const float* __restrict__ bf) {
    const int row = blockIdx.x;
    float4* x4 = (float4*)(g_hbuf + (size_t)row * (NHD * FGD));
    float4 v[4];
    float s = 0.f, ss = 0.f;
#pragma unroll
    for (int k = 0; k < 4; k++) {
        v[k] = x4[threadIdx.x + k * 256];
        s  += v[k].x + v[k].y + v[k].z + v[k].w;
        ss += v[k].x * v[k].x + v[k].y * v[k].y + v[k].z * v[k].z + v[k].w * v[k].w;
    }
    block_reduce2(s, ss);
    float m  = s * (1.f / 4096.f);
    float rs = rsqrtf(ss * (1.f / 4096.f) - m * m + 1e-6f);
    const float4* g4 = (const float4*)gf;
    const float4* b4 = (const float4*)bf;
#pragma unroll
    for (int k = 0; k < 4; k++) {
        int c4 = threadIdx.x + k * 256;
        float4 gv = g4[c4], bv = b4[c4], xv = v[k];
        float4 o;
        o.x = fmaxf((xv.x - m) * rs * gv.x + bv.x, 0.f);
        o.y = fmaxf((xv.y - m) * rs * gv.y + bv.y, 0.f);
        o.z = fmaxf((xv.z - m) * rs * gv.z + bv.z, 0.f);
        o.w = fmaxf((xv.w - m) * rs * gv.w + bv.w, 0.f);
        x4[c4] = o;
    }
}

// ---------------- combine: out = lci*lcg_g + ig_g*x + rci*rcg_g ----------------
__global__ void __launch_bounds__(256) combine_k() {
    size_t i4 = (size_t)blockIdx.x * 256 + threadIdx.x;   // over ROWS*256 float4s
    size_t row = i4 >> 8;
    int c4 = (int)(i4 & 255);
    int c = c4 * 4, h = c >> 7, ig = c & 127;
    const float* gb = g_gbuf + row * (NHD * TGD) + h * TGD;
    float4 lg  = *(const float4*)(gb + ig);
    float4 igv = *(const float4*)(gb + 128 + ig);
    float4 rg  = *(const float4*)(gb + 256 + ig);
    float4 li  = *((const float4*)(g_lci  + row * ISZ) + c4);
    float4 ri  = *((const float4*)(g_rci  + row * ISZ) + c4);
    float4 xv  = *((const float4*)(g_xbuf + row * ISZ) + c4);
    float4 o;
    o.x = li.x * lg.x + igv.x * xv.x + ri.x * rg.x;
    o.y = li.y * lg.y + igv.y * xv.y + ri.y * rg.y;
    o.z = li.z * lg.z + igv.z * xv.z + ri.z * rg.z;
    o.w = li.w * lg.w + igv.w * xv.w + ri.w * rg.w;
    *((float4*)(g_pre + row * ISZ) + c4) = o;
}

// ---------------- host ----------------
extern "C" void kernel_launch(void* const* d_in, const int* in_sizes, int n_in,
                              void* d_out, int out_size) {
    const float* inputs = (const float*)d_in[0];
    const unsigned char* mask = (const unsigned char*)d_in[1];
    const float* W_csum = (const float*)d_in[2];
    const float* b_csum = (const float*)d_in[3];
    const float* W_x    = (const float*)d_in[4];
    const float* b_x    = (const float*)d_in[5];
    const float* gl     = (const float*)d_in[6];
    const float* bel    = (const float*)d_in[7];
    const float* gr     = (const float*)d_in[8];
    const float* ber    = (const float*)d_in[9];
    const float* ggain  = (const float*)d_in[10];
    const float* beg    = (const float*)d_in[11];
    const float* gf     = (const float*)d_in[12];
    const float* bef    = (const float*)d_in[13];
    const float* W_g    = (const float*)d_in[14];
    const float* b_g    = (const float*)d_in[15];
    const float* W_f1   = (const float*)d_in[16];
    const float* b_f1   = (const float*)d_in[17];
    const float* W_f2   = (const float*)d_in[18];
    const float* b_f2   = (const float*)d_in[19];
    const float* W_o    = (const float*)d_in[20];
    const float* b_o    = (const float*)d_in[21];
    float* out = (float*)d_out;

    float *p_csum, *p_cell, *p_g, *p_h, *p_x, *p_pre;
    cudaGetSymbolAddress((void**)&p_csum, g_csum);
    cudaGetSymbolAddress((void**)&p_cell, g_cell);
    cudaGetSymbolAddress((void**)&p_g,    g_gbuf);
    cudaGetSymbolAddress((void**)&p_h,    g_hbuf);
    cudaGetSymbolAddress((void**)&p_x,    g_xbuf);
    cudaGetSymbolAddress((void**)&p_pre,  g_pre);

    dim3 blk(256);

    // 1) out_csum = inputs @ W_csum + b_csum ; masked rows -> 0
    sgemm_k<1><<<dim3(32, 128, 1), blk>>>(inputs, ISZ, 0, W_csum, 0, b_csum, 0,
                                          p_csum, CH, 0, CH, ISZ, mask, nullptr);
    // 2) out_x = inputs @ W_x + b_x, scattered into cell_i middle slots
    sgemm_k<4><<<dim3(8, 128, 1), blk>>>(inputs, ISZ, 0, W_x, 0, b_x, 0,
                                         p_cell, NHD * TGD, 0, ISZ, ISZ, nullptr, nullptr);
    // 3) fwd/rev cumsum along S, in place
    cumsum_k<<<64, 256>>>(p_csum);
    // 4) LN(lc), LN(rc) -> cell_i gate slots + relu'd lci/rci
    ln_lcrc_k<<<dim3(ROWS, 2), 256>>>(gl, bel, gr, ber);
    // 5) per-head gates GEMM: cell_i @ W_g + b_g
    sgemm_k<0><<<dim3(3, 128, 8), blk>>>(p_cell, NHD * TGD, TGD, W_g, (long)TGD * TGD,
                                         b_g, TGD, p_g, NHD * TGD, TGD, TGD, TGD,
                                         nullptr, nullptr);
    // 6) LN over all 3072 gates + sigmoid
    ln_g_k<<<ROWS, 256>>>(ggain, beg);
    // 7) per-head ffn1: cell_i @ W_f1 + b_f1
    sgemm_k<0><<<dim3(4, 128, 8), blk>>>(p_cell, NHD * TGD, TGD, W_f1, (long)TGD * FGD,
                                         b_f1, FGD, p_h, NHD * FGD, FGD, FGD, TGD,
                                         nullptr, nullptr);
    // 8) LN over 4096 + relu
    ln_f_k<<<ROWS, 256>>>(gf, bef);
    // 9) per-head ffn2: h @ W_f2 + b_f2
    sgemm_k<0><<<dim3(1, 128, 8), blk>>>(p_h, NHD * FGD, FGD, W_f2, (long)FGD * IGD,
                                         b_f2, IGD, p_x, ISZ, IGD, IGD, FGD,
                                         nullptr, nullptr);
    // 10) gating combine
    combine_k<<<ROWS, 256>>>();
    // 11) final: pre @ W_o + b_o + inputs
    sgemm_k<2><<<dim3(8, 128, 1), blk>>>(p_pre, ISZ, 0, W_o, 0, b_o, 0,
                                         out, ISZ, 0, ISZ, ISZ, nullptr, inputs);
}

// round 4
// speedup vs baseline: 2.7538x; 2.7538x over previous
#include <cuda_runtime.h>
#include <cuda_bf16.h>
#include <cstdint>

#define ROWS 16384      // B*S
#define CH   4096
#define NHD  8
#define IGD  128
#define TGD  384
#define FGD  512
#define ISZ  1024

// ---------------- fp32 scratch ----------------
__device__ float g_csum[(size_t)ROWS * CH];        // cumsum in place
__device__ float g_gbuf[(size_t)ROWS * NHD * TGD]; // gates fp32
__device__ float g_hbuf[(size_t)ROWS * NHD * FGD]; // ffn hidden fp32 (pre-LN)
__device__ float g_lci [(size_t)ROWS * ISZ];
__device__ float g_rci [(size_t)ROWS * ISZ];
__device__ float g_xbuf[(size_t)ROWS * ISZ];

// ---------------- split bf16 planes (hi/lo) ----------------
__device__ __align__(16) uint16_t is_h [(size_t)ROWS * ISZ];
__device__ __align__(16) uint16_t is_l [(size_t)ROWS * ISZ];
__device__ __align__(16) uint16_t cell_h[(size_t)ROWS * NHD * TGD];
__device__ __align__(16) uint16_t cell_l[(size_t)ROWS * NHD * TGD];
__device__ __align__(16) uint16_t hp_h [(size_t)ROWS * NHD * FGD];
__device__ __align__(16) uint16_t hp_l [(size_t)ROWS * NHD * FGD];
__device__ __align__(16) uint16_t pre_h[(size_t)ROWS * ISZ];
__device__ __align__(16) uint16_t pre_l[(size_t)ROWS * ISZ];
// transposed weight planes [N][K]
__device__ __align__(16) uint16_t wcs_h[(size_t)CH * ISZ];
__device__ __align__(16) uint16_t wcs_l[(size_t)CH * ISZ];
__device__ __align__(16) uint16_t wx_h [(size_t)ISZ * ISZ];
__device__ __align__(16) uint16_t wx_l [(size_t)ISZ * ISZ];
__device__ __align__(16) uint16_t wg_h [(size_t)NHD * TGD * TGD];
__device__ __align__(16) uint16_t wg_l [(size_t)NHD * TGD * TGD];
__device__ __align__(16) uint16_t wf1_h[(size_t)NHD * FGD * TGD];
__device__ __align__(16) uint16_t wf1_l[(size_t)NHD * FGD * TGD];
__device__ __align__(16) uint16_t wf2_h[(size_t)NHD * IGD * FGD];
__device__ __align__(16) uint16_t wf2_l[(size_t)NHD * IGD * FGD];
__device__ __align__(16) uint16_t wo_h [(size_t)ISZ * ISZ];
__device__ __align__(16) uint16_t wo_l [(size_t)ISZ * ISZ];

// ---------------- helpers ----------------
__device__ __forceinline__ uint32_t smem_u32(const void* p) {
    uint32_t a;
    asm("{ .reg .u64 t; cvta.to.shared.u64 t, %1; cvt.u32.u64 %0, t; }" : "=r"(a) : "l"(p));
    return a;
}
#define CP16(dst, src) asm volatile("cp.async.cg.shared.global [%0], [%1], 16;" :: "r"(dst), "l"(src))
#define CP_COMMIT()    asm volatile("cp.async.commit_group;" ::: "memory")
#define CP_WAIT0()     asm volatile("cp.async.wait_group 0;" ::: "memory")

__device__ __forceinline__ void ldm4(uint32_t& r0, uint32_t& r1, uint32_t& r2, uint32_t& r3, uint32_t a) {
    asm volatile("ldmatrix.sync.aligned.m8n8.x4.shared.b16 {%0,%1,%2,%3}, [%4];"
                 : "=r"(r0), "=r"(r1), "=r"(r2), "=r"(r3) : "r"(a));
}
__device__ __forceinline__ void mma16816(float* d, const uint32_t* a, const uint32_t* b) {
    asm volatile("mma.sync.aligned.m16n8k16.row.col.f32.bf16.bf16.f32 "
                 "{%0,%1,%2,%3},{%4,%5,%6,%7},{%8,%9},{%0,%1,%2,%3};"
                 : "+f"(d[0]), "+f"(d[1]), "+f"(d[2]), "+f"(d[3])
                 : "r"(a[0]), "r"(a[1]), "r"(a[2]), "r"(a[3]), "r"(b[0]), "r"(b[1]));
}
__device__ __forceinline__ void splitf(float x, uint16_t& h, uint16_t& l) {
    __nv_bfloat16 hb = __float2bfloat16(x);
    float r = x - __bfloat162float(hb);
    __nv_bfloat16 lb = __float2bfloat16(r);
    h = *(uint16_t*)&hb;
    l = *(uint16_t*)&lb;
}
__device__ __forceinline__ void split4(float4 v, uint2& h, uint2& l) {
    uint16_t h0, l0, h1, l1, h2, l2, h3, l3;
    splitf(v.x, h0, l0); splitf(v.y, h1, l1); splitf(v.z, h2, l2); splitf(v.w, h3, l3);
    h.x = (uint32_t)h0 | ((uint32_t)h1 << 16);
    h.y = (uint32_t)h2 | ((uint32_t)h3 << 16);
    l.x = (uint32_t)l0 | ((uint32_t)l1 << 16);
    l.y = (uint32_t)l2 | ((uint32_t)l3 << 16);
}

// ---------------- bf16x3 tensor-core GEMM ----------------
// C[M,N] = A[M,K] @ B^T (B planes stored [N][K]); FLAGS: 1 mask, 2 residual, 4 split-out w/ remap
// SMEM tiles: 128 rows x 128 bytes, swizzled: addr = row*128 + ((col16 ^ (row&7))<<4)
#define OFF_AH 0
#define OFF_AL 16384
#define OFF_BH 32768
#define OFF_BL 49152
#define SMT    65536

template <int FLAGS>
__global__ void __launch_bounds__(256, 2) hgemm_k(
    const uint16_t* __restrict__ Ah, const uint16_t* __restrict__ Al, int lda, int aoff,
    const uint16_t* __restrict__ Bh, const uint16_t* __restrict__ Bl, long boff,
    const float* __restrict__ bias, int biasoff,
    float* __restrict__ C, int ldc, int coff,
    uint16_t* __restrict__ Ch, uint16_t* __restrict__ Cl,
    int N, int K,
    const unsigned char* __restrict__ mask,
    const float* __restrict__ resid)
{
    extern __shared__ char smem[];
    const uint32_t sb = smem_u32(smem);
    const int tid = threadIdx.x, wid = tid >> 5, lane = tid & 31;

    Ah += (long)blockIdx.z * aoff;  Al += (long)blockIdx.z * aoff;
    Bh += (long)blockIdx.z * boff;  Bl += (long)blockIdx.z * boff;
    bias += (long)blockIdx.z * biasoff;
    C  += (long)blockIdx.z * coff;

    const int m0 = blockIdx.y * 128;
    const int n0 = blockIdx.x * 128;
    const int warpM = (wid & 1) * 64;
    const int warpN = (wid >> 1) * 32;

    // consumer bases (row part only; column swizzled per k-step)
    const int rowA = warpM + (lane & 15);
    const int hiA  = (lane >> 4) & 1;
    const int sA   = rowA & 7;
    const uint32_t aRowH = sb + OFF_AH + (uint32_t)rowA * 128;
    const uint32_t aRowL = sb + OFF_AL + (uint32_t)rowA * 128;

    const int rowB = warpN + (lane & 7) + ((lane & 16) >> 1);
    const int hiB  = (lane >> 3) & 1;
    const int sB   = rowB & 7;
    const uint32_t bRowH = sb + OFF_BH + (uint32_t)rowB * 128;
    const uint32_t bRowL = sb + OFF_BL + (uint32_t)rowB * 128;

    float acc[4][4][4];
#pragma unroll
    for (int i = 0; i < 4; i++)
#pragma unroll
        for (int j = 0; j < 4; j++)
#pragma unroll
            for (int q = 0; q < 4; q++) acc[i][j][q] = 0.f;

    const int nch = K >> 6;
    for (int c = 0; c < nch; c++) {
        const int k0 = c << 6;
        // stage: 1024 16B copies per plane-pair; each thread 4 rows-segments
#pragma unroll
        for (int t = 0; t < 4; t++) {
            int u = tid + t * 256;
            int row = u >> 3, c16 = u & 7;
            uint32_t d = (uint32_t)row * 128 + (((uint32_t)(c16 ^ (row & 7))) << 4);
            size_t sa = (size_t)(m0 + row) * lda + k0 + c16 * 8;
            CP16(sb + OFF_AH + d, Ah + sa);
            CP16(sb + OFF_AL + d, Al + sa);
            size_t sbn = (size_t)(n0 + row) * K + k0 + c16 * 8;
            CP16(sb + OFF_BH + d, Bh + sbn);
            CP16(sb + OFF_BL + d, Bl + sbn);
        }
        CP_COMMIT();
        CP_WAIT0();
        __syncthreads();

#pragma unroll
        for (int ks = 0; ks < 4; ks++) {
            const uint32_t ca = ((uint32_t)((2 * ks + hiA) ^ sA)) << 4;
            const uint32_t cb = ((uint32_t)((2 * ks + hiB) ^ sB)) << 4;
            uint32_t bh[4][2], bl[4][2];
            ldm4(bh[0][0], bh[0][1], bh[1][0], bh[1][1], bRowH + cb);
            ldm4(bh[2][0], bh[2][1], bh[3][0], bh[3][1], bRowH + 2048 + cb);
            ldm4(bl[0][0], bl[0][1], bl[1][0], bl[1][1], bRowL + cb);
            ldm4(bl[2][0], bl[2][1], bl[3][0], bl[3][1], bRowL + 2048 + cb);
#pragma unroll
            for (int mf = 0; mf < 4; mf++) {
                uint32_t ah[4], al[4];
                ldm4(ah[0], ah[1], ah[2], ah[3], aRowH + mf * 2048 + ca);
                ldm4(al[0], al[1], al[2], al[3], aRowL + mf * 2048 + ca);
#pragma unroll
                for (int nf = 0; nf < 4; nf++) {
                    mma16816(acc[mf][nf], ah, bh[nf]);
                    mma16816(acc[mf][nf], ah, bl[nf]);
                    mma16816(acc[mf][nf], al, bh[nf]);
                }
            }
        }
        __syncthreads();
    }

    // ---------------- epilogue ----------------
#pragma unroll
    for (int mf = 0; mf < 4; mf++) {
        long rA = m0 + warpM + mf * 16 + (lane >> 2);
        long rB = rA + 8;
        float zfA = 1.f, zfB = 1.f;
        if (FLAGS & 1) { zfA = mask[rA] ? 0.f : 1.f; zfB = mask[rB] ? 0.f : 1.f; }
#pragma unroll
        for (int nf = 0; nf < 4; nf++) {
            int gn = n0 + warpN + nf * 8 + (lane & 3) * 2;
            float b0 = bias[gn], b1 = bias[gn + 1];
            float x0 = acc[mf][nf][0] + b0, x1 = acc[mf][nf][1] + b1;
            float y0 = acc[mf][nf][2] + b0, y1 = acc[mf][nf][3] + b1;
            if (FLAGS & 1) { x0 *= zfA; x1 *= zfA; y0 *= zfB; y1 *= zfB; }
            if (FLAGS & 2) {
                x0 += resid[rA * N + gn]; x1 += resid[rA * N + gn + 1];
                y0 += resid[rB * N + gn]; y1 += resid[rB * N + gn + 1];
            }
            if (FLAGS & 4) {
                int cn = (gn >> 7) * TGD + IGD + (gn & 127);
                uint16_t h0, l0, h1, l1;
                splitf(x0, h0, l0); splitf(x1, h1, l1);
                *(uint32_t*)&Ch[rA * ldc + cn] = (uint32_t)h0 | ((uint32_t)h1 << 16);
                *(uint32_t*)&Cl[rA * ldc + cn] = (uint32_t)l0 | ((uint32_t)l1 << 16);
                splitf(y0, h0, l0); splitf(y1, h1, l1);
                *(uint32_t*)&Ch[rB * ldc + cn] = (uint32_t)h0 | ((uint32_t)h1 << 16);
                *(uint32_t*)&Cl[rB * ldc + cn] = (uint32_t)l0 | ((uint32_t)l1 << 16);
            } else {
                *(float2*)(C + rA * ldc + gn) = make_float2(x0, x1);
                *(float2*)(C + rB * ldc + gn) = make_float2(y0, y1);
            }
        }
    }
}

// ---------------- conversion kernels ----------------
__global__ void __launch_bounds__(256) isplit_k(const float* __restrict__ src,
                                                uint16_t* __restrict__ h,
                                                uint16_t* __restrict__ l) {
    size_t i = (size_t)blockIdx.x * 256 + threadIdx.x;
    float4 v = ((const float4*)src)[i];
    uint2 hh, ll;
    split4(v, hh, ll);
    ((uint2*)h)[i] = hh;
    ((uint2*)l)[i] = ll;
}

// W [K][N] fp32 -> planes [N][K]
__global__ void __launch_bounds__(256) wsplit_k(const float* __restrict__ W,
                                                uint16_t* __restrict__ Th,
                                                uint16_t* __restrict__ Tl,
                                                int K, int N) {
    __shared__ float tile[32][33];
    const int n0 = blockIdx.x * 32, k0 = blockIdx.y * 32;
    const float* Wp = W + (size_t)blockIdx.z * K * N;
    uint16_t* Hh = Th + (size_t)blockIdx.z * K * N;
    uint16_t* Hl = Tl + (size_t)blockIdx.z * K * N;
    int tx = threadIdx.x & 31, ty = threadIdx.x >> 5;
#pragma unroll
    for (int i = 0; i < 4; i++)
        tile[ty + 8 * i][tx] = Wp[(size_t)(k0 + ty + 8 * i) * N + n0 + tx];
    __syncthreads();
#pragma unroll
    for (int i = 0; i < 4; i++) {
        float v = tile[tx][ty + 8 * i];
        uint16_t h, l;
        splitf(v, h, l);
        size_t o = (size_t)(n0 + ty + 8 * i) * K + k0 + tx;
        Hh[o] = h; Hl[o] = l;
    }
}

// ---------------- block reduce ----------------
__device__ __forceinline__ void block_reduce2(float& a, float& b) {
    __shared__ float sh[64];
    int lane = threadIdx.x & 31, wid = threadIdx.x >> 5;
#pragma unroll
    for (int o = 16; o > 0; o >>= 1) {
        a += __shfl_xor_sync(0xffffffffu, a, o);
        b += __shfl_xor_sync(0xffffffffu, b, o);
    }
    if (lane == 0) { sh[wid] = a; sh[32 + wid] = b; }
    __syncthreads();
    if (threadIdx.x < 32) {
        a = (lane < 8) ? sh[lane] : 0.f;
        b = (lane < 8) ? sh[32 + lane] : 0.f;
#pragma unroll
        for (int o = 4; o > 0; o >>= 1) {
            a += __shfl_xor_sync(0xffffffffu, a, o);
            b += __shfl_xor_sync(0xffffffffu, b, o);
        }
        if (lane == 0) { sh[0] = a; sh[32] = b; }
    }
    __syncthreads();
    a = sh[0]; b = sh[32];
}

// ---------------- cumsum ----------------
__global__ void __launch_bounds__(256) cumsum_k(float* __restrict__ buf) {
    int idx = blockIdx.x * 256 + threadIdx.x;
    int b = idx >> 12, c = idx & 4095;
    float* p = buf + ((size_t)b << 24) + c;
    float acc = 0.f;
    if (c < 2048) {
#pragma unroll 8
        for (int s = 0; s < 4096; s++) { acc += p[(size_t)s * CH]; p[(size_t)s * CH] = acc; }
    } else {
#pragma unroll 8
        for (int s = 4095; s >= 0; s--) { acc += p[(size_t)s * CH]; p[(size_t)s * CH] = acc; }
    }
}

// ---------------- LN lc/rc -> cell planes + relu'd lci/rci ----------------
__global__ void __launch_bounds__(256) ln_lcrc_k(
    const float* __restrict__ gl, const float* __restrict__ bl,
    const float* __restrict__ gr, const float* __restrict__ br_)
{
    const int row = blockIdx.x, side = blockIdx.y;
    const float4* x4 = (const float4*)(g_csum + (size_t)row * CH + side * 2048);
    float4 v[2];
    float s = 0.f, ss = 0.f;
#pragma unroll
    for (int k = 0; k < 2; k++) {
        v[k] = x4[threadIdx.x + k * 256];
        s  += v[k].x + v[k].y + v[k].z + v[k].w;
        ss += v[k].x * v[k].x + v[k].y * v[k].y + v[k].z * v[k].z + v[k].w * v[k].w;
    }
    block_reduce2(s, ss);
    float m  = s * (1.f / 2048.f);
    float rs = rsqrtf(ss * (1.f / 2048.f) - m * m + 1e-6f);

    const float4* g4 = (const float4*)(side ? gr  : gl);
    const float4* b4 = (const float4*)(side ? br_ : bl);
    float* ibuf = side ? g_rci : g_lci;
#pragma unroll
    for (int k = 0; k < 2; k++) {
        int c4 = threadIdx.x + k * 256;
        int c  = c4 * 4;
        float4 gv = g4[c4], bv = b4[c4], xv = v[k];
        float4 o;
        o.x = (xv.x - m) * rs * gv.x + bv.x;
        o.y = (xv.y - m) * rs * gv.y + bv.y;
        o.z = (xv.z - m) * rs * gv.z + bv.z;
        o.w = (xv.w - m) * rs * gv.w + bv.w;
        if (c < 1024) {
            int h = c >> 7, ig = c & 127;
            size_t o16 = (size_t)row * (NHD * TGD) + h * TGD + side * 256 + ig;
            uint2 hh, ll;
            split4(o, hh, ll);
            *(uint2*)&cell_h[o16] = hh;
            *(uint2*)&cell_l[o16] = ll;
        } else {
            o.x = fmaxf(o.x, 0.f); o.y = fmaxf(o.y, 0.f);
            o.z = fmaxf(o.z, 0.f); o.w = fmaxf(o.w, 0.f);
            *(float4*)(ibuf + (size_t)row * ISZ + (c - 1024)) = o;
        }
    }
}

// ---------------- LN gates + sigmoid (fp32 in place) ----------------
__global__ void __launch_bounds__(256) ln_g_k(const float* __restrict__ gg,
                                              const float* __restrict__ bg) {
    const int row = blockIdx.x;
    float4* x4 = (float4*)(g_gbuf + (size_t)row * (NHD * TGD));
    float4 v[3];
    float s = 0.f, ss = 0.f;
#pragma unroll
    for (int k = 0; k < 3; k++) {
        v[k] = x4[threadIdx.x + k * 256];
        s  += v[k].x + v[k].y + v[k].z + v[k].w;
        ss += v[k].x * v[k].x + v[k].y * v[k].y + v[k].z * v[k].z + v[k].w * v[k].w;
    }
    block_reduce2(s, ss);
    float m  = s * (1.f / 3072.f);
    float rs = rsqrtf(ss * (1.f / 3072.f) - m * m + 1e-6f);
    const float4* g4 = (const float4*)gg;
    const float4* b4 = (const float4*)bg;
#pragma unroll
    for (int k = 0; k < 3; k++) {
        int c4 = threadIdx.x + k * 256;
        float4 gv = g4[c4], bv = b4[c4], xv = v[k];
        float4 o;
        o.x = 1.f / (1.f + expf(-((xv.x - m) * rs * gv.x + bv.x)));
        o.y = 1.f / (1.f + expf(-((xv.y - m) * rs * gv.y + bv.y)));
        o.z = 1.f / (1.f + expf(-((xv.z - m) * rs * gv.z + bv.z)));
        o.w = 1.f / (1.f + expf(-((xv.w - m) * rs * gv.w + bv.w)));
        x4[c4] = o;
    }
}

// ---------------- LN ffn hidden + relu -> h planes ----------------
__global__ void __launch_bounds__(256) ln_f_k(const float* __restrict__ gf,
                                              const float* __restrict__ bf) {
    const int row = blockIdx.x;
    const float4* x4 = (const float4*)(g_hbuf + (size_t)row * (NHD * FGD));
    float4 v[4];
    float s = 0.f, ss = 0.f;
#pragma unroll
    for (int k = 0; k < 4; k++) {
        v[k] = x4[threadIdx.x + k * 256];
        s  += v[k].x + v[k].y + v[k].z + v[k].w;
        ss += v[k].x * v[k].x + v[k].y * v[k].y + v[k].z * v[k].z + v[k].w * v[k].w;
    }
    block_reduce2(s, ss);
    float m  = s * (1.f / 4096.f);
    float rs = rsqrtf(ss * (1.f / 4096.f) - m * m + 1e-6f);
    const float4* g4 = (const float4*)gf;
    const float4* b4 = (const float4*)bf;
#pragma unroll
    for (int k = 0; k < 4; k++) {
        int c4 = threadIdx.x + k * 256;
        float4 gv = g4[c4], bv = b4[c4], xv = v[k];
        float4 o;
        o.x = fmaxf((xv.x - m) * rs * gv.x + bv.x, 0.f);
        o.y = fmaxf((xv.y - m) * rs * gv.y + bv.y, 0.f);
        o.z = fmaxf((xv.z - m) * rs * gv.z + bv.z, 0.f);
        o.w = fmaxf((xv.w - m) * rs * gv.w + bv.w, 0.f);
        size_t o16 = (size_t)row * (NHD * FGD) + c4 * 4;
        uint2 hh, ll;
        split4(o, hh, ll);
        *(uint2*)&hp_h[o16] = hh;
        *(uint2*)&hp_l[o16] = ll;
    }
}

// ---------------- combine -> pre planes ----------------
__global__ void __launch_bounds__(256) combine_k() {
    size_t i4 = (size_t)blockIdx.x * 256 + threadIdx.x;
    size_t row = i4 >> 8;
    int c4 = (int)(i4 & 255);
    int c = c4 * 4, h = c >> 7, ig = c & 127;
    const float* gb = g_gbuf + row * (NHD * TGD) + h * TGD;
    float4 lg  = *(const float4*)(gb + ig);
    float4 igv = *(const float4*)(gb + 128 + ig);
    float4 rg  = *(const float4*)(gb + 256 + ig);
    float4 li  = *((const float4*)(g_lci  + row * ISZ) + c4);
    float4 ri  = *((const float4*)(g_rci  + row * ISZ) + c4);
    float4 xv  = *((const float4*)(g_xbuf + row * ISZ) + c4);
    float4 o;
    o.x = li.x * lg.x + igv.x * xv.x + ri.x * rg.x;
    o.y = li.y * lg.y + igv.y * xv.y + ri.y * rg.y;
    o.z = li.z * lg.z + igv.z * xv.z + ri.z * rg.z;
    o.w = li.w * lg.w + igv.w * xv.w + ri.w * rg.w;
    uint2 hh, ll;
    split4(o, hh, ll);
    *(uint2*)&pre_h[row * ISZ + c] = hh;
    *(uint2*)&pre_l[row * ISZ + c] = ll;
}

// ---------------- host ----------------
extern "C" void kernel_launch(void* const* d_in, const int* in_sizes, int n_in,
                              void* d_out, int out_size) {
    const float* inputs = (const float*)d_in[0];
    const unsigned char* mask = (const unsigned char*)d_in[1];
    const float* W_csum = (const float*)d_in[2];
    const float* b_csum = (const float*)d_in[3];
    const float* W_x    = (const float*)d_in[4];
    const float* b_x    = (const float*)d_in[5];
    const float* gl     = (const float*)d_in[6];
    const float* bel    = (const float*)d_in[7];
    const float* gr     = (const float*)d_in[8];
    const float* ber    = (const float*)d_in[9];
    const float* ggain  = (const float*)d_in[10];
    const float* beg    = (const float*)d_in[11];
    const float* gf     = (const float*)d_in[12];
    const float* bef    = (const float*)d_in[13];
    const float* W_g    = (const float*)d_in[14];
    const float* b_g    = (const float*)d_in[15];
    const float* W_f1   = (const float*)d_in[16];
    const float* b_f1   = (const float*)d_in[17];
    const float* W_f2   = (const float*)d_in[18];
    const float* b_f2   = (const float*)d_in[19];
    const float* W_o    = (const float*)d_in[20];
    const float* b_o    = (const float*)d_in[21];
    float* out = (float*)d_out;

    float *p_csum, *p_g, *p_h, *p_x;
    cudaGetSymbolAddress((void**)&p_csum, g_csum);
    cudaGetSymbolAddress((void**)&p_g,    g_gbuf);
    cudaGetSymbolAddress((void**)&p_h,    g_hbuf);
    cudaGetSymbolAddress((void**)&p_x,    g_xbuf);
    uint16_t *pish, *pisl, *pch, *pcl, *phh, *phl, *pph, *ppl;
    uint16_t *pwcsh, *pwcsl, *pwxh, *pwxl, *pwgh, *pwgl, *pwf1h, *pwf1l, *pwf2h, *pwf2l, *pwoh, *pwol;
    cudaGetSymbolAddress((void**)&pish, is_h);   cudaGetSymbolAddress((void**)&pisl, is_l);
    cudaGetSymbolAddress((void**)&pch,  cell_h); cudaGetSymbolAddress((void**)&pcl,  cell_l);
    cudaGetSymbolAddress((void**)&phh,  hp_h);   cudaGetSymbolAddress((void**)&phl,  hp_l);
    cudaGetSymbolAddress((void**)&pph,  pre_h);  cudaGetSymbolAddress((void**)&ppl,  pre_l);
    cudaGetSymbolAddress((void**)&pwcsh, wcs_h); cudaGetSymbolAddress((void**)&pwcsl, wcs_l);
    cudaGetSymbolAddress((void**)&pwxh,  wx_h);  cudaGetSymbolAddress((void**)&pwxl,  wx_l);
    cudaGetSymbolAddress((void**)&pwgh,  wg_h);  cudaGetSymbolAddress((void**)&pwgl,  wg_l);
    cudaGetSymbolAddress((void**)&pwf1h, wf1_h); cudaGetSymbolAddress((void**)&pwf1l, wf1_l);
    cudaGetSymbolAddress((void**)&pwf2h, wf2_h); cudaGetSymbolAddress((void**)&pwf2l, wf2_l);
    cudaGetSymbolAddress((void**)&pwoh,  wo_h);  cudaGetSymbolAddress((void**)&pwol,  wo_l);

    cudaFuncSetAttribute(hgemm_k<0>, cudaFuncAttributeMaxDynamicSharedMemorySize, SMT);
    cudaFuncSetAttribute(hgemm_k<1>, cudaFuncAttributeMaxDynamicSharedMemorySize, SMT);
    cudaFuncSetAttribute(hgemm_k<2>, cudaFuncAttributeMaxDynamicSharedMemorySize, SMT);
    cudaFuncSetAttribute(hgemm_k<4>, cudaFuncAttributeMaxDynamicSharedMemorySize, SMT);

    dim3 blk(256);

    // ---- conversions ----
    isplit_k<<<ROWS * ISZ / 1024, blk>>>(inputs, pish, pisl);
    wsplit_k<<<dim3(CH / 32, ISZ / 32, 1), blk>>>(W_csum, pwcsh, pwcsl, ISZ, CH);
    wsplit_k<<<dim3(ISZ / 32, ISZ / 32, 1), blk>>>(W_x, pwxh, pwxl, ISZ, ISZ);
    wsplit_k<<<dim3(TGD / 32, TGD / 32, NHD), blk>>>(W_g, pwgh, pwgl, TGD, TGD);
    wsplit_k<<<dim3(FGD / 32, TGD / 32, NHD), blk>>>(W_f1, pwf1h, pwf1l, TGD, FGD);
    wsplit_k<<<dim3(IGD / 32, FGD / 32, NHD), blk>>>(W_f2, pwf2h, pwf2l, FGD, IGD);
    wsplit_k<<<dim3(ISZ / 32, ISZ / 32, 1), blk>>>(W_o, pwoh, pwol, ISZ, ISZ);

    // 1) csum GEMM (masked)
    hgemm_k<1><<<dim3(CH / 128, ROWS / 128, 1), blk, SMT>>>(
        pish, pisl, ISZ, 0, pwcsh, pwcsl, 0, b_csum, 0,
        p_csum, CH, 0, nullptr, nullptr, CH, ISZ, mask, nullptr);
    // 2) out_x GEMM -> cell planes (remap)
    hgemm_k<4><<<dim3(ISZ / 128, ROWS / 128, 1), blk, SMT>>>(
        pish, pisl, ISZ, 0, pwxh, pwxl, 0, b_x, 0,
        nullptr, NHD * TGD, 0, pch, pcl, ISZ, ISZ, nullptr, nullptr);
    // 3) cumsum
    cumsum_k<<<64, 256>>>(p_csum);
    // 4) LN lc/rc
    ln_lcrc_k<<<dim3(ROWS, 2), 256>>>(gl, bel, gr, ber);
    // 5) gates GEMM
    hgemm_k<0><<<dim3(TGD / 128, ROWS / 128, NHD), blk, SMT>>>(
        pch, pcl, NHD * TGD, TGD, pwgh, pwgl, (long)TGD * TGD, b_g, TGD,
        p_g, NHD * TGD, TGD, nullptr, nullptr, TGD, TGD, nullptr, nullptr);
    // 6) LN gates + sigmoid
    ln_g_k<<<ROWS, 256>>>(ggain, beg);
    // 7) ffn1 GEMM
    hgemm_k<0><<<dim3(FGD / 128, ROWS / 128, NHD), blk, SMT>>>(
        pch, pcl, NHD * TGD, TGD, pwf1h, pwf1l, (long)FGD * TGD, b_f1, FGD,
        p_h, NHD * FGD, FGD, nullptr, nullptr, FGD, TGD, nullptr, nullptr);
    // 8) LN ffn + relu -> h planes
    ln_f_k<<<ROWS, 256>>>(gf, bef);
    // 9) ffn2 GEMM
    hgemm_k<0><<<dim3(IGD / 128, ROWS / 128, NHD), blk, SMT>>>(
        phh, phl, NHD * FGD, FGD, pwf2h, pwf2l, (long)IGD * FGD, b_f2, IGD,
        p_x, ISZ, IGD, nullptr, nullptr, IGD, FGD, nullptr, nullptr);
    // 10) combine -> pre planes
    combine_k<<<ROWS, 256>>>();
    // 11) final GEMM + residual
    hgemm_k<2><<<dim3(ISZ / 128, ROWS / 128, 1), blk, SMT>>>(
        pph, ppl, ISZ, 0, pwoh, pwol, 0, b_o, 0,
        out, ISZ, 0, nullptr, nullptr, ISZ, ISZ, nullptr, inputs);
}